// round 13
// baseline (speedup 1.0000x reference)
#include <cuda_runtime.h>
#include <cuda_fp16.h>
#include <cstdint>

// ---------------------------------------------------------------------------
// VectorQuantize forward: persistent fp16 mma.sync screen, 16 warps/CTA
// (4/SMSP for latency hiding), codes split in 4 quarters across warp groups,
// norm folded into MMA accumulator init (d-space keys), pair-merge top-3
// tracking + 4-way triple merge + pruned fp64 exact rescore of near-ties.
//
//   z_e   : [B=32, D=64, H=64, W=64] f32
//   embed : [K=1024, D=64] f32
// Output (f32): [0,8388608) z_q_st | [8388608] loss | [8388609,8519681) idx
//
// d = x.e - (||e||^2 + 1024)/2 is always negative -> raw fp32 bits are
// order-reversed (min-uint = best). Low 10 key bits carry the code index
// (quantum <= 0.0625 in d-space, covered by THETA_D + rescore).
// ---------------------------------------------------------------------------

#define DD    64
#define HW    4096
#define NTOK  131072
#define KK    1024
#define TPB   512                 // 16 warps: 4 token groups x 4 code quarters
#define MT    128                 // tokens per job
#define NJOBS (NTOK / MT)         // 1024
#define GRID  148                 // persistent CTAs (one per SM)

#define ZQ_ELEMS 8388608UL
#define LOSS_OFF 8388608UL
#define IDX_OFF  8388609UL

#define ESTRIDE 144               // codebook row stride (bytes)
#define SM_ES   0                           // fp16 codebook, 1024x144 = 147456
#define SM_EN   (KK * ESTRIDE)              // -(||e||^2+C)/2 fp32 [1024], 4096
#define SM_XS   (SM_EN + KK * 4)            // X fp32 [64][128], 32768
#define SM_EG   (SM_XS + DD * MT * 4)       // gathered rows [128][65], 33280
#define SM_TOP  SM_EG                       // OVERLAY: triples [128][3][12], 18432
                                            // (Top fully consumed before Eg writes)
#define SM_SIDX (SM_EG + MT * 65 * 4)       // winner per token, 512
#define SM_RED  (SM_SIDX + MT * 4)          // loss reduction, 64
#define SMEM_TOTAL (SM_RED + 64)            // 218176 B

#define CPOS    1024.0f
#define THETA_D 0.15f             // d-space: quantum 0.0625 + 6*sigma + margin

__device__ float g_part[GRID];

// Insert a fresh pair of scores into a sorted-3 (min-uint best) in 10 ops.
__device__ __forceinline__ void upd_pair(uint32_t& k1, uint32_t& k2, uint32_t& k3,
                                         float d0, float d1, uint32_t n0) {
    uint32_t u0 = (__float_as_uint(d0) & 0xFFFFFC00u) | n0;
    uint32_t u1 = (__float_as_uint(d1) & 0xFFFFFC00u) | (n0 + 1u);
    uint32_t s1 = min(u0, u1);
    uint32_t s2 = max(u0, u1);
    uint32_t h  = max(k1, s1);
    k1 = min(k1, s1);
    uint32_t l2 = min(k2, s2);
    k2 = min(h, l2);
    k3 = min(k3, max(h, l2));
}
// Merge two sorted triples, keep sorted top-3 of the union (7 ops).
__device__ __forceinline__ void merge33(uint32_t& a1, uint32_t& a2, uint32_t& a3,
                                        uint32_t b1, uint32_t b2, uint32_t b3) {
    uint32_t m1 = min(a1, b1);
    uint32_t x  = max(a1, b1);
    uint32_t mn = min(a2, b2);
    uint32_t mx = max(a2, b2);
    uint32_t m2 = min(x, mn);
    uint32_t y  = max(x, mn);
    uint32_t m3 = min(min(y, mx), min(a3, b3));
    a1 = m1; a2 = m2; a3 = m3;
}
__device__ __forceinline__ float key2f(uint32_t k) {
    return __uint_as_float(k & 0xFFFFFC00u);   // negative float d-hat
}

// ---------------------------------------------------------------------------
__global__ __launch_bounds__(TPB, 1)
void vq_main_kernel(const float* __restrict__ z_e,
                    const float* __restrict__ embed,
                    float* __restrict__ out) {
    extern __shared__ __align__(16) char smem[];
    float* en_s = (float*)(smem + SM_EN);
    float* Xs   = (float*)(smem + SM_XS);
    float* Eg   = (float*)(smem + SM_EG);
    uint32_t* Top = (uint32_t*)(smem + SM_TOP);
    int*   Sidx = (int*)(smem + SM_SIDX);
    float* Red  = (float*)(smem + SM_RED);

    const int tid = threadIdx.x, wid = tid >> 5, lane = tid & 31;
    const int g = lane >> 2, tig = lane & 3;
    const int q = wid >> 2;                    // code quarter 0..3
    const int qbase = q * 256;
    const int trow0 = (wid & 3) * 32;          // token group per warp

    // ---- Stage codebook ONCE per CTA: fp16, MMA-fragment-ordered rows ----
    for (int r = tid; r < KK; r += TPB) {
        const float4* row = (const float4*)(embed + (size_t)r * DD);
        char* dst = smem + SM_ES + r * ESTRIDE;
        float s = CPOS;
        uint32_t w[32];
#pragma unroll
        for (int i = 0; i < 16; i++) {
            float4 v = __ldg(row + i);
            s = fmaf(v.x, v.x, s); s = fmaf(v.y, v.y, s);
            s = fmaf(v.z, v.z, s); s = fmaf(v.w, v.w, s);
            __half2 h0 = __floats2half2_rn(v.x, v.y);
            __half2 h1 = __floats2half2_rn(v.z, v.w);
            w[2 * i]     = *(uint32_t*)&h0;
            w[2 * i + 1] = *(uint32_t*)&h1;
        }
#pragma unroll
        for (int tg = 0; tg < 4; tg++)
#pragma unroll
            for (int hf = 0; hf < 2; hf++) {
                uint4 qq = make_uint4(w[tg + 4 * hf], w[8 + tg + 4 * hf],
                                      w[16 + tg + 4 * hf], w[24 + tg + 4 * hf]);
                *(uint4*)(dst + tg * 32 + hf * 16) = qq;
            }
        en_s[r] = -(s) * 0.5f;     // -(||e||^2 + C)/2
    }

    float lacc = 0.f;              // per-thread loss partial across jobs

    for (int job = blockIdx.x; job < NJOBS; job += GRID) {
        const int base = job * MT;
        const int b = base >> 12, hw0 = base & 4095;
        const float* zbase = z_e + (size_t)b * DD * HW + hw0;
        __syncthreads();           // prior job done with Xs/Eg

        // ---- Stage X (coalesced): Xs[d][t] ----
        for (int i = tid; i < DD * MT; i += TPB)
            Xs[i] = zbase[(size_t)(i >> 7) * HW + (i & 127)];
        __syncthreads();

        // ---- Build fp16 A fragments (32 tokens per warp) ----
        uint32_t A[4][2][4];
#pragma unroll
        for (int kt = 0; kt < 4; kt++)
#pragma unroll
            for (int mt = 0; mt < 2; mt++) {
                const int ta = trow0 + mt * 16 + g, tb = ta + 8;
                const int c0 = kt * 16 + tig * 2;
#pragma unroll
                for (int h = 0; h < 2; h++) {
                    const int cc = c0 + h * 8;
                    __half2 pa = __floats2half2_rn(Xs[cc * MT + ta],
                                                   Xs[(cc + 1) * MT + ta]);
                    __half2 pb = __floats2half2_rn(Xs[cc * MT + tb],
                                                   Xs[(cc + 1) * MT + tb]);
                    A[kt][mt][2 * h]     = *(uint32_t*)&pa;
                    A[kt][mt][2 * h + 1] = *(uint32_t*)&pb;
                }
            }

        // ---- Screen: 32 n-tiles of 8 codes (this warp's quarter) ----
        uint32_t k1[4], k2[4], k3[4];
#pragma unroll
        for (int r = 0; r < 4; r++) { k1[r] = k2[r] = k3[r] = 0xFFFFFFFFu; }

        const char* brow = smem + SM_ES + (qbase + g) * ESTRIDE + tig * 32;
        const float2* enp = (const float2*)(en_s + qbase + tig * 2);
        uint32_t ncur = (uint32_t)(qbase + tig * 2);

#pragma unroll 4
        for (int nt = 0; nt < 32; nt++) {
            const uint4 Bv0 = *(const uint4*)(brow);        // B0 kt0..3
            const uint4 Bv1 = *(const uint4*)(brow + 16);   // B1 kt0..3
            const float2 en2 = *enp;
#pragma unroll
            for (int mt = 0; mt < 2; mt++) {
                float d0 = en2.x, d1 = en2.y, d2 = en2.x, d3 = en2.y;
#define VQ_MMA(b0, b1, kt) \
                asm volatile( \
                    "mma.sync.aligned.m16n8k16.row.col.f32.f16.f16.f32 " \
                    "{%0,%1,%2,%3}, {%4,%5,%6,%7}, {%8,%9}, {%0,%1,%2,%3};" \
                    : "+f"(d0), "+f"(d1), "+f"(d2), "+f"(d3) \
                    : "r"(A[kt][mt][0]), "r"(A[kt][mt][1]), \
                      "r"(A[kt][mt][2]), "r"(A[kt][mt][3]), \
                      "r"(b0), "r"(b1))
                VQ_MMA(Bv0.x, Bv1.x, 0);
                VQ_MMA(Bv0.y, Bv1.y, 1);
                VQ_MMA(Bv0.z, Bv1.z, 2);
                VQ_MMA(Bv0.w, Bv1.w, 3);
#undef VQ_MMA
                upd_pair(k1[mt*2],   k2[mt*2],   k3[mt*2],   d0, d1, ncur);
                upd_pair(k1[mt*2+1], k2[mt*2+1], k3[mt*2+1], d2, d3, ncur);
            }
            brow += 8 * ESTRIDE;
            enp  += 4;
            ncur += 8;
        }

        // ---- Cross-quarter merge: quarters 1-3 publish, quarter 0 resolves ----
        if (q != 0) {
#pragma unroll
            for (int r = 0; r < 4; r++) {
                const int lt = trow0 + (r >> 1) * 16 + g + ((r & 1) ? 8 : 0);
                uint32_t* tp = Top + lt * 36 + (q - 1) * 12 + tig * 3;
                tp[0] = k1[r]; tp[1] = k2[r]; tp[2] = k3[r];
            }
        }
        __syncthreads();

        if (q == 0) {
#pragma unroll
            for (int r = 0; r < 4; r++) {
                const int lt = trow0 + (r >> 1) * 16 + g + ((r & 1) ? 8 : 0);
                uint32_t m1 = k1[r], m2 = k2[r], m3 = k3[r];
#pragma unroll
                for (int pq = 0; pq < 3; pq++) {
                    const uint32_t* tp = Top + lt * 36 + pq * 12 + tig * 3;
                    merge33(m1, m2, m3, tp[0], tp[1], tp[2]);
                }

                // quad-merge top-2 for the gap test
                uint32_t a1 = m1, a2 = m2;
#pragma unroll
                for (int off = 1; off < 4; off <<= 1) {
                    uint32_t b1 = __shfl_xor_sync(0xFFFFFFFFu, a1, off);
                    uint32_t b2 = __shfl_xor_sync(0xFFFFFFFFu, a2, off);
                    uint32_t q1 = min(a1, b1);
                    uint32_t q2 = min(max(a1, b1), min(a2, b2));
                    a1 = q1; a2 = q2;
                }
                int winner;
                const float a1f = key2f(a1);
                const bool need = (a1f - key2f(a2)) < THETA_D;  // quad-uniform
                if (need) {
                    const float cut = a1f - THETA_D;
                    double bs = 1e300; int bi = 1 << 20;
                    const uint32_t kr[3] = { m1, m2, m3 };
#pragma unroll
                    for (int cc = 0; cc < 3; cc++) {
                        if (key2f(kr[cc]) >= cut) {
                            const int idx = (int)(kr[cc] & 1023u);
                            const float4* er = (const float4*)(embed + (size_t)idx * DD);
                            double nrm = 0.0, dot = 0.0;
#pragma unroll
                            for (int i = 0; i < 16; i++) {
                                float4 v = __ldg(er + i);
                                double e0 = v.x, e1 = v.y, e2 = v.z, e3 = v.w;
                                nrm = fma(e0, e0, nrm); nrm = fma(e1, e1, nrm);
                                nrm = fma(e2, e2, nrm); nrm = fma(e3, e3, nrm);
                                dot = fma(e0, (double)Xs[(4*i+0) * MT + lt], dot);
                                dot = fma(e1, (double)Xs[(4*i+1) * MT + lt], dot);
                                dot = fma(e2, (double)Xs[(4*i+2) * MT + lt], dot);
                                dot = fma(e3, (double)Xs[(4*i+3) * MT + lt], dot);
                            }
                            double sc = nrm - 2.0 * dot;
                            if (sc < bs || (sc == bs && idx < bi)) { bs = sc; bi = idx; }
                        }
                    }
                    const uint32_t qmask = 0xFu << (lane & 28);
#pragma unroll
                    for (int off = 1; off < 4; off <<= 1) {
                        double os = __shfl_xor_sync(qmask, bs, off);
                        int    oi = __shfl_xor_sync(qmask, bi, off);
                        if (os < bs || (os == bs && oi < bi)) { bs = os; bi = oi; }
                    }
                    winner = bi;
                } else {
                    winner = (int)(a1 & 1023u);
                }
                if (tig == 0) {
                    Sidx[lt] = winner;
                    out[IDX_OFF + (size_t)(base + lt)] = (float)winner;
                }
            }
        }
        __syncthreads();

        // ---- Epilogue: gather (4 threads/row), float2 straight-through ----
        {
            const int t = tid >> 2, hf = tid & 3;
            const int bi = Sidx[t];
            const float4* er = (const float4*)(embed + (size_t)bi * DD) + hf * 4;
#pragma unroll
            for (int i = 0; i < 4; i++) {
                float4 v = __ldg(er + i);
                float* eg = Eg + t * 65 + hf * 16 + 4 * i;
                eg[0] = v.x; eg[1] = v.y; eg[2] = v.z; eg[3] = v.w;
            }
        }
        __syncthreads();

        for (int i = tid; i < DD * MT / 2; i += TPB) {
            const int d = i >> 6, t2 = (i & 63) * 2;
            float2 xv = *(const float2*)(Xs + d * MT + t2);
            float df0 = Eg[t2 * 65 + d] - xv.x;
            float df1 = Eg[(t2 + 1) * 65 + d] - xv.y;
            lacc = fmaf(df0, df0, lacc);
            lacc = fmaf(df1, df1, lacc);
            float2 o2 = make_float2(xv.x + df0, xv.y + df1);
            *(float2*)(out + (size_t)b * DD * HW + (size_t)d * HW + hw0 + t2) = o2;
        }
    }

    // ---- CTA loss partial (deterministic; no atomics) ----
#pragma unroll
    for (int o = 16; o > 0; o >>= 1) lacc += __shfl_down_sync(0xFFFFFFFFu, lacc, o);
    __syncthreads();
    if (lane == 0) Red[wid] = lacc;
    __syncthreads();
    if (wid == 0) {
        float v = (lane < TPB / 32) ? Red[lane] : 0.f;
#pragma unroll
        for (int o = 8; o > 0; o >>= 1) v += __shfl_down_sync(0xFFFFFFFFu, v, o);
        if (lane == 0) g_part[blockIdx.x] = v;
    }
}

// Sum the 148 per-CTA partials (deterministic order) and write the loss.
__global__ void vq_finalize_kernel(float* __restrict__ out) {
    __shared__ float red[8];
    const int tid = threadIdx.x, lane = tid & 31, wid = tid >> 5;
    float v = (tid < GRID) ? g_part[tid] : 0.f;
#pragma unroll
    for (int o = 16; o > 0; o >>= 1) v += __shfl_down_sync(0xFFFFFFFFu, v, o);
    if (lane == 0) red[wid] = v;
    __syncthreads();
    if (wid == 0) {
        float s = (lane < 8) ? red[lane] : 0.f;
#pragma unroll
        for (int o = 4; o > 0; o >>= 1) s += __shfl_down_sync(0xFFFFFFFFu, s, o);
        if (lane == 0) out[LOSS_OFF] = s / (float)((size_t)NTOK * DD);
    }
}

extern "C" void kernel_launch(void* const* d_in, const int* in_sizes, int n_in,
                              void* d_out, int out_size) {
    const float* z_e   = (const float*)d_in[0];
    const float* embed = (const float*)d_in[1];
    float* out = (float*)d_out;

    cudaFuncSetAttribute(vq_main_kernel,
                         cudaFuncAttributeMaxDynamicSharedMemorySize, SMEM_TOTAL);
    vq_main_kernel<<<GRID, TPB, SMEM_TOTAL>>>(z_e, embed, out);
    vq_finalize_kernel<<<1, 256>>>(out);
}

// round 14
// speedup vs baseline: 1.0588x; 1.0588x over previous
#include <cuda_runtime.h>
#include <cuda_fp16.h>
#include <cstdint>

// ---------------------------------------------------------------------------
// VectorQuantize forward: persistent fp16 mma.sync screen, 16 warps/CTA,
// codes split in 4 quarters, norm folded into MMA accumulator init (d-space
// keys), pair-merge top-3 + all-warp 4-quarter resolve + pruned fp64 exact
// rescore of near-ties + software-pipelined X staging.
//
//   z_e   : [B=32, D=64, H=64, W=64] f32
//   embed : [K=1024, D=64] f32
// Output (f32): [0,8388608) z_q_st | [8388608] loss | [8388609,8519681) idx
// ---------------------------------------------------------------------------

#define DD    64
#define HW    4096
#define NTOK  131072
#define KK    1024
#define TPB   512                 // 16 warps: 4 token groups x 4 code quarters
#define MT    128                 // tokens per job
#define NJOBS (NTOK / MT)         // 1024
#define GRID  148                 // persistent CTAs (one per SM)

#define ZQ_ELEMS 8388608UL
#define LOSS_OFF 8388608UL
#define IDX_OFF  8388609UL

#define ESTRIDE 144               // codebook row stride (bytes)
#define SM_ES   0                           // fp16 codebook, 1024x144 = 147456
#define SM_EN   (KK * ESTRIDE)              // -(||e||^2+C)/2 fp32 [1024], 4096
#define SM_XS   (SM_EN + KK * 4)            // X fp32 [64][128], 32768
#define SM_EG   (SM_XS + DD * MT * 4)       // gathered rows [128][65], 33280
#define SM_TOP  SM_EG                       // OVERLAY: triples [128][4][4][3], 24576
                                            // (Top fully consumed before Eg writes)
#define SM_SIDX (SM_EG + MT * 65 * 4)       // winner per token, 512
#define SM_RED  (SM_SIDX + MT * 4)          // loss reduction, 64
#define SMEM_TOTAL (SM_RED + 64)            // 218176 B

#define CPOS    1024.0f
#define THETA_D 0.15f             // d-space: quantum 0.0625 + 6*sigma + margin

__device__ float g_part[GRID];

// Insert a fresh pair of scores into a sorted-3 (min-uint best) in 10 ops.
__device__ __forceinline__ void upd_pair(uint32_t& k1, uint32_t& k2, uint32_t& k3,
                                         float d0, float d1, uint32_t n0) {
    uint32_t u0 = (__float_as_uint(d0) & 0xFFFFFC00u) | n0;
    uint32_t u1 = (__float_as_uint(d1) & 0xFFFFFC00u) | (n0 + 1u);
    uint32_t s1 = min(u0, u1);
    uint32_t s2 = max(u0, u1);
    uint32_t h  = max(k1, s1);
    k1 = min(k1, s1);
    uint32_t l2 = min(k2, s2);
    k2 = min(h, l2);
    k3 = min(k3, max(h, l2));
}
// Merge two sorted triples, keep sorted top-3 of the union (7 ops).
__device__ __forceinline__ void merge33(uint32_t& a1, uint32_t& a2, uint32_t& a3,
                                        uint32_t b1, uint32_t b2, uint32_t b3) {
    uint32_t m1 = min(a1, b1);
    uint32_t x  = max(a1, b1);
    uint32_t mn = min(a2, b2);
    uint32_t mx = max(a2, b2);
    uint32_t m2 = min(x, mn);
    uint32_t y  = max(x, mn);
    uint32_t m3 = min(min(y, mx), min(a3, b3));
    a1 = m1; a2 = m2; a3 = m3;
}
__device__ __forceinline__ float key2f(uint32_t k) {
    return __uint_as_float(k & 0xFFFFFC00u);   // negative float d-hat
}

// ---------------------------------------------------------------------------
__global__ __launch_bounds__(TPB, 1)
void vq_main_kernel(const float* __restrict__ z_e,
                    const float* __restrict__ embed,
                    float* __restrict__ out) {
    extern __shared__ __align__(16) char smem[];
    float* en_s = (float*)(smem + SM_EN);
    float* Xs   = (float*)(smem + SM_XS);
    float* Eg   = (float*)(smem + SM_EG);
    uint32_t* Top = (uint32_t*)(smem + SM_TOP);
    int*   Sidx = (int*)(smem + SM_SIDX);
    float* Red  = (float*)(smem + SM_RED);

    const int tid = threadIdx.x, wid = tid >> 5, lane = tid & 31;
    const int g = lane >> 2, tig = lane & 3;
    const int q = wid >> 2;                    // code quarter 0..3
    const int qbase = q * 256;
    const int trow0 = (wid & 3) * 32;          // token group per warp

    // ---- Stage codebook ONCE per CTA: fp16, MMA-fragment-ordered rows ----
    for (int r = tid; r < KK; r += TPB) {
        const float4* row = (const float4*)(embed + (size_t)r * DD);
        char* dst = smem + SM_ES + r * ESTRIDE;
        float s = CPOS;
        uint32_t w[32];
#pragma unroll
        for (int i = 0; i < 16; i++) {
            float4 v = __ldg(row + i);
            s = fmaf(v.x, v.x, s); s = fmaf(v.y, v.y, s);
            s = fmaf(v.z, v.z, s); s = fmaf(v.w, v.w, s);
            __half2 h0 = __floats2half2_rn(v.x, v.y);
            __half2 h1 = __floats2half2_rn(v.z, v.w);
            w[2 * i]     = *(uint32_t*)&h0;
            w[2 * i + 1] = *(uint32_t*)&h1;
        }
#pragma unroll
        for (int tg = 0; tg < 4; tg++)
#pragma unroll
            for (int hf = 0; hf < 2; hf++) {
                uint4 qq = make_uint4(w[tg + 4 * hf], w[8 + tg + 4 * hf],
                                      w[16 + tg + 4 * hf], w[24 + tg + 4 * hf]);
                *(uint4*)(dst + tg * 32 + hf * 16) = qq;
            }
        en_s[r] = -(s) * 0.5f;     // -(||e||^2 + C)/2
    }

    // ---- Prologue: stage X for the first job ----
    {
        const int base0 = blockIdx.x * MT;
        const float* zb0 = z_e + (size_t)(base0 >> 12) * DD * HW + (base0 & 4095);
        for (int i = tid; i < DD * MT; i += TPB)
            Xs[i] = zb0[(size_t)(i >> 7) * HW + (i & 127)];
    }

    float lacc = 0.f;              // per-thread loss partial across jobs

    for (int job = blockIdx.x; job < NJOBS; job += GRID) {
        const int base = job * MT;
        const int b = base >> 12, hw0 = base & 4095;
        __syncthreads();           // Xs ready; Eg/Top free

        // ---- Build fp16 A fragments (32 tokens per warp) ----
        uint32_t A[4][2][4];
#pragma unroll
        for (int kt = 0; kt < 4; kt++)
#pragma unroll
            for (int mt = 0; mt < 2; mt++) {
                const int ta = trow0 + mt * 16 + g, tb = ta + 8;
                const int c0 = kt * 16 + tig * 2;
#pragma unroll
                for (int h = 0; h < 2; h++) {
                    const int cc = c0 + h * 8;
                    __half2 pa = __floats2half2_rn(Xs[cc * MT + ta],
                                                   Xs[(cc + 1) * MT + ta]);
                    __half2 pb = __floats2half2_rn(Xs[cc * MT + tb],
                                                   Xs[(cc + 1) * MT + tb]);
                    A[kt][mt][2 * h]     = *(uint32_t*)&pa;
                    A[kt][mt][2 * h + 1] = *(uint32_t*)&pb;
                }
            }

        // ---- Screen: 32 n-tiles of 8 codes (this warp's quarter) ----
        uint32_t k1[4], k2[4], k3[4];
#pragma unroll
        for (int r = 0; r < 4; r++) { k1[r] = k2[r] = k3[r] = 0xFFFFFFFFu; }

        const char* brow = smem + SM_ES + (qbase + g) * ESTRIDE + tig * 32;
        const float2* enp = (const float2*)(en_s + qbase + tig * 2);
        uint32_t ncur = (uint32_t)(qbase + tig * 2);

#pragma unroll 4
        for (int nt = 0; nt < 32; nt++) {
            const uint4 Bv0 = *(const uint4*)(brow);        // B0 kt0..3
            const uint4 Bv1 = *(const uint4*)(brow + 16);   // B1 kt0..3
            const float2 en2 = *enp;
#pragma unroll
            for (int mt = 0; mt < 2; mt++) {
                float d0 = en2.x, d1 = en2.y, d2 = en2.x, d3 = en2.y;
#define VQ_MMA(b0, b1, kt) \
                asm volatile( \
                    "mma.sync.aligned.m16n8k16.row.col.f32.f16.f16.f32 " \
                    "{%0,%1,%2,%3}, {%4,%5,%6,%7}, {%8,%9}, {%0,%1,%2,%3};" \
                    : "+f"(d0), "+f"(d1), "+f"(d2), "+f"(d3) \
                    : "r"(A[kt][mt][0]), "r"(A[kt][mt][1]), \
                      "r"(A[kt][mt][2]), "r"(A[kt][mt][3]), \
                      "r"(b0), "r"(b1))
                VQ_MMA(Bv0.x, Bv1.x, 0);
                VQ_MMA(Bv0.y, Bv1.y, 1);
                VQ_MMA(Bv0.z, Bv1.z, 2);
                VQ_MMA(Bv0.w, Bv1.w, 3);
#undef VQ_MMA
                upd_pair(k1[mt*2],   k2[mt*2],   k3[mt*2],   d0, d1, ncur);
                upd_pair(k1[mt*2+1], k2[mt*2+1], k3[mt*2+1], d2, d3, ncur);
            }
            brow += 8 * ESTRIDE;
            enp  += 4;
            ncur += 8;
        }

        // ---- ALL warps publish their sorted triples ----
#pragma unroll
        for (int r = 0; r < 4; r++) {
            const int lt = trow0 + (r >> 1) * 16 + g + ((r & 1) ? 8 : 0);
            uint32_t* tp = Top + lt * 48 + q * 12 + tig * 3;
            tp[0] = k1[r]; tp[1] = k2[r]; tp[2] = k3[r];
        }

        // ---- Prefetch next job's X into registers (overlaps resolve etc) ----
        const bool hasnext = (job + GRID) < NJOBS;
        float xr[16];
        if (hasnext) {
            const int bn = (job + GRID) * MT;
            const float* zn = z_e + (size_t)(bn >> 12) * DD * HW + (bn & 4095);
#pragma unroll
            for (int k = 0; k < 16; k++) {
                const int i = k * TPB + tid;
                xr[k] = __ldg(&zn[(size_t)(i >> 7) * HW + (i & 127)]);
            }
        }
        __syncthreads();

        // ---- Resolve: warp (q,tg) handles row r=q of its token group ----
        {
            const int r = q;
            const int lt = trow0 + (r >> 1) * 16 + g + ((r & 1) ? 8 : 0);
            const uint32_t* tp = Top + lt * 48 + tig * 3;
            uint32_t m1 = tp[0], m2 = tp[1], m3 = tp[2];
#pragma unroll
            for (int pq = 1; pq < 4; pq++)
                merge33(m1, m2, m3, tp[pq * 12], tp[pq * 12 + 1], tp[pq * 12 + 2]);

            // quad-merge top-2 for the gap test
            uint32_t a1 = m1, a2 = m2;
#pragma unroll
            for (int off = 1; off < 4; off <<= 1) {
                uint32_t b1 = __shfl_xor_sync(0xFFFFFFFFu, a1, off);
                uint32_t b2 = __shfl_xor_sync(0xFFFFFFFFu, a2, off);
                uint32_t q1 = min(a1, b1);
                uint32_t q2 = min(max(a1, b1), min(a2, b2));
                a1 = q1; a2 = q2;
            }
            int winner;
            const float a1f = key2f(a1);
            const bool need = (a1f - key2f(a2)) < THETA_D;  // quad-uniform
            if (need) {
                const float cut = a1f - THETA_D;
                double bs = 1e300; int bi = 1 << 20;
                const uint32_t kr[3] = { m1, m2, m3 };
#pragma unroll
                for (int cc = 0; cc < 3; cc++) {
                    if (key2f(kr[cc]) >= cut) {
                        const int idx = (int)(kr[cc] & 1023u);
                        const float4* er = (const float4*)(embed + (size_t)idx * DD);
                        double nrm = 0.0, dot = 0.0;
#pragma unroll
                        for (int i = 0; i < 16; i++) {
                            float4 v = __ldg(er + i);
                            double e0 = v.x, e1 = v.y, e2 = v.z, e3 = v.w;
                            nrm = fma(e0, e0, nrm); nrm = fma(e1, e1, nrm);
                            nrm = fma(e2, e2, nrm); nrm = fma(e3, e3, nrm);
                            dot = fma(e0, (double)Xs[(4*i+0) * MT + lt], dot);
                            dot = fma(e1, (double)Xs[(4*i+1) * MT + lt], dot);
                            dot = fma(e2, (double)Xs[(4*i+2) * MT + lt], dot);
                            dot = fma(e3, (double)Xs[(4*i+3) * MT + lt], dot);
                        }
                        double sc = nrm - 2.0 * dot;
                        if (sc < bs || (sc == bs && idx < bi)) { bs = sc; bi = idx; }
                    }
                }
                const uint32_t qmask = 0xFu << (lane & 28);
#pragma unroll
                for (int off = 1; off < 4; off <<= 1) {
                    double os = __shfl_xor_sync(qmask, bs, off);
                    int    oi = __shfl_xor_sync(qmask, bi, off);
                    if (os < bs || (os == bs && oi < bi)) { bs = os; bi = oi; }
                }
                winner = bi;
            } else {
                winner = (int)(a1 & 1023u);
            }
            if (tig == 0) {
                Sidx[lt] = winner;
                out[IDX_OFF + (size_t)(base + lt)] = (float)winner;
            }
        }
        __syncthreads();

        // ---- Gather winner rows (4 threads/row) into Eg ----
        {
            const int t = tid >> 2, hf = tid & 3;
            const int bi = Sidx[t];
            const float4* er = (const float4*)(embed + (size_t)bi * DD) + hf * 4;
#pragma unroll
            for (int i = 0; i < 4; i++) {
                float4 v = __ldg(er + i);
                float* eg = Eg + t * 65 + hf * 16 + 4 * i;
                eg[0] = v.x; eg[1] = v.y; eg[2] = v.z; eg[3] = v.w;
            }
        }
        __syncthreads();

        // ---- Loss + straight-through output ----
        for (int i = tid; i < DD * MT / 2; i += TPB) {
            const int d = i >> 6, t2 = (i & 63) * 2;
            float2 xv = *(const float2*)(Xs + d * MT + t2);
            float df0 = Eg[t2 * 65 + d] - xv.x;
            float df1 = Eg[(t2 + 1) * 65 + d] - xv.y;
            lacc = fmaf(df0, df0, lacc);
            lacc = fmaf(df1, df1, lacc);
            float2 o2 = make_float2(xv.x + df0, xv.y + df1);
            *(float2*)(out + (size_t)b * DD * HW + (size_t)d * HW + hw0 + t2) = o2;
        }
        __syncthreads();           // Xs reads done before overwrite

        if (hasnext) {
#pragma unroll
            for (int k = 0; k < 16; k++) Xs[k * TPB + tid] = xr[k];
        }
    }

    // ---- CTA loss partial (deterministic; no atomics) ----
#pragma unroll
    for (int o = 16; o > 0; o >>= 1) lacc += __shfl_down_sync(0xFFFFFFFFu, lacc, o);
    __syncthreads();
    if (lane == 0) Red[wid] = lacc;
    __syncthreads();
    if (wid == 0) {
        float v = (lane < TPB / 32) ? Red[lane] : 0.f;
#pragma unroll
        for (int o = 8; o > 0; o >>= 1) v += __shfl_down_sync(0xFFFFFFFFu, v, o);
        if (lane == 0) g_part[blockIdx.x] = v;
    }
}

// Sum the 148 per-CTA partials (deterministic order) and write the loss.
__global__ void vq_finalize_kernel(float* __restrict__ out) {
    __shared__ float red[8];
    const int tid = threadIdx.x, lane = tid & 31, wid = tid >> 5;
    float v = (tid < GRID) ? g_part[tid] : 0.f;
#pragma unroll
    for (int o = 16; o > 0; o >>= 1) v += __shfl_down_sync(0xFFFFFFFFu, v, o);
    if (lane == 0) red[wid] = v;
    __syncthreads();
    if (wid == 0) {
        float s = (lane < 8) ? red[lane] : 0.f;
#pragma unroll
        for (int o = 4; o > 0; o >>= 1) s += __shfl_down_sync(0xFFFFFFFFu, s, o);
        if (lane == 0) out[LOSS_OFF] = s / (float)((size_t)NTOK * DD);
    }
}

extern "C" void kernel_launch(void* const* d_in, const int* in_sizes, int n_in,
                              void* d_out, int out_size) {
    const float* z_e   = (const float*)d_in[0];
    const float* embed = (const float*)d_in[1];
    float* out = (float*)d_out;

    cudaFuncSetAttribute(vq_main_kernel,
                         cudaFuncAttributeMaxDynamicSharedMemorySize, SMEM_TOTAL);
    vq_main_kernel<<<GRID, TPB, SMEM_TOTAL>>>(z_e, embed, out);
    vq_finalize_kernel<<<1, 256>>>(out);
}